// round 11
// baseline (speedup 1.0000x reference)
#include <cuda_runtime.h>
#include <cuda_fp16.h>
#include <math.h>
#include <stdint.h>

#define NROWS 8192
#define FIN   512
#define FOUT  64
#define ALPHA 0.2f
#define JSPLIT 4
#define JCHUNK (NROWS / JSPLIT)
#define NTILES (JCHUNK / 64)

// Scratch (no cudaMalloc allowed)
__device__ __align__(16) float  g_h[NROWS * FOUT];    // h = x @ W (fp32)
__device__ __align__(16) __half g_hT[FOUT * NROWS];   // h transposed, fp16: [col][row]
__device__ float  g_a1[NROWS];
__device__ float  g_a2[NROWS];
__device__ float  g_e1p[NROWS], g_e1n[NROWS];           // per-row factors (fp32)
__device__ __align__(16) __half g_a2h[NROWS];           // fp16 copies for k3
__device__ __align__(16) __half g_e2ph[NROWS];
__device__ __align__(16) __half g_e2nh[NROWS];
__device__ __align__(16) float g_pacc[JSPLIT][NROWS * FOUT];
__device__ float  g_pden[JSPLIT][NROWS];

__device__ __forceinline__ unsigned h2u(__half2 h) { return *(unsigned*)&h; }
__device__ __forceinline__ __half2 u2h(unsigned u) { return *(__half2*)&u; }

__device__ __forceinline__ uint32_t smem_u32(const void* p) {
    uint32_t a;
    asm("{ .reg .u64 t; cvta.to.shared.u64 t, %1; cvt.u32.u64 %0, t; }" : "=r"(a) : "l"(p));
    return a;
}

__device__ __forceinline__ void mma_f16(float c[4],
                                        unsigned a0, unsigned a1, unsigned a2, unsigned a3,
                                        unsigned b0, unsigned b1) {
    asm volatile(
        "mma.sync.aligned.m16n8k16.row.col.f32.f16.f16.f32 "
        "{%0,%1,%2,%3}, {%4,%5,%6,%7}, {%8,%9}, {%0,%1,%2,%3};"
        : "+f"(c[0]), "+f"(c[1]), "+f"(c[2]), "+f"(c[3])
        : "r"(a0), "r"(a1), "r"(a2), "r"(a3), "r"(b0), "r"(b1));
}

__device__ __forceinline__ void ldsm_x4(unsigned& r0, unsigned& r1,
                                        unsigned& r2, unsigned& r3, uint32_t addr) {
    asm volatile("ldmatrix.sync.aligned.m8n8.x4.shared.b16 {%0,%1,%2,%3}, [%4];"
                 : "=r"(r0), "=r"(r1), "=r"(r2), "=r"(r3) : "r"(addr));
}

// ---------------------------------------------------------------------------
// K1: h = x @ W   (8192x512 @ 512x64), FP32, 64x64 CTA tile, 4x4 per thread
// ---------------------------------------------------------------------------
__global__ __launch_bounds__(256) void k1_gemm(const float* __restrict__ x,
                                               const float* __restrict__ W) {
    __shared__ __align__(16) float xT[32][68];
    __shared__ __align__(16) float Ws[32][68];
    const int tid = threadIdx.x;
    const int ty = tid >> 4, tx = tid & 15;
    const int row0 = blockIdx.x * 64;

    float acc[4][4];
#pragma unroll
    for (int i = 0; i < 4; i++)
#pragma unroll
        for (int j = 0; j < 4; j++) acc[i][j] = 0.f;

    for (int k0 = 0; k0 < FIN; k0 += 32) {
#pragma unroll
        for (int l = 0; l < 2; l++) {
            int idx = tid * 2 + l;
            int r = idx >> 3;
            int kq = (idx & 7) << 2;
            float4 v = *(const float4*)(x + (size_t)(row0 + r) * FIN + k0 + kq);
            xT[kq + 0][r] = v.x; xT[kq + 1][r] = v.y;
            xT[kq + 2][r] = v.z; xT[kq + 3][r] = v.w;
        }
#pragma unroll
        for (int l = 0; l < 2; l++) {
            int idx = tid * 2 + l;
            int kk = idx >> 4;
            int cq = (idx & 15) << 2;
            *(float4*)&Ws[kk][cq] = *(const float4*)(W + (size_t)(k0 + kk) * FOUT + cq);
        }
        __syncthreads();
#pragma unroll
        for (int kk = 0; kk < 32; kk++) {
            float4 xa = *(const float4*)&xT[kk][ty * 4];
            float4 wb = *(const float4*)&Ws[kk][tx * 4];
            float av[4] = {xa.x, xa.y, xa.z, xa.w};
            float bv[4] = {wb.x, wb.y, wb.z, wb.w};
#pragma unroll
            for (int i = 0; i < 4; i++)
#pragma unroll
                for (int j = 0; j < 4; j++)
                    acc[i][j] = fmaf(av[i], bv[j], acc[i][j]);
        }
        __syncthreads();
    }
#pragma unroll
    for (int i = 0; i < 4; i++) {
        float4 v = make_float4(acc[i][0], acc[i][1], acc[i][2], acc[i][3]);
        *(float4*)(g_h + (size_t)(row0 + ty * 4 + i) * FOUT + tx * 4) = v;
    }
}

// ---------------------------------------------------------------------------
// K1t: g_hT[col][row] = (half)g_h[row][col]. Scalar SMEM stores (pitch 65).
// ---------------------------------------------------------------------------
__global__ __launch_bounds__(256) void k1t_trans() {
    __shared__ float ht[64][65];
    const int tid = threadIdx.x;
    const int row0 = blockIdx.x * 64;
    {
        const int r = tid >> 2, cp = (tid & 3) * 16;
#pragma unroll
        for (int l = 0; l < 4; l++) {
            float4 v = *(const float4*)(g_h + (size_t)(row0 + r) * FOUT + cp + l * 4);
            ht[r][cp + l * 4 + 0] = v.x;
            ht[r][cp + l * 4 + 1] = v.y;
            ht[r][cp + l * 4 + 2] = v.z;
            ht[r][cp + l * 4 + 3] = v.w;
        }
    }
    __syncthreads();
    {
        const int c = tid >> 2, rp = (tid & 3) * 16;
        unsigned u[8];
#pragma unroll
        for (int i = 0; i < 8; i++) {
            __half2 h2 = __floats2half2_rn(ht[rp + i * 2][c], ht[rp + i * 2 + 1][c]);
            u[i] = *(unsigned*)&h2;
        }
        __half* dst = g_hT + (size_t)c * NROWS + row0 + rp;
        ((uint4*)dst)[0] = make_uint4(u[0], u[1], u[2], u[3]);
        ((uint4*)dst)[1] = make_uint4(u[4], u[5], u[6], u[7]);
    }
}

// ---------------------------------------------------------------------------
// K2: a1/a2 row projections. One warp per row.
// ---------------------------------------------------------------------------
__global__ __launch_bounds__(256) void k2_att(const float* __restrict__ a) {
    const int warp = (blockIdx.x * blockDim.x + threadIdx.x) >> 5;
    const int lane = threadIdx.x & 31;
    if (warp >= NROWS) return;
    const float* hrow = g_h + (size_t)warp * FOUT;
    float v0 = hrow[lane], v1 = hrow[lane + 32];
    float s1 = v0 * a[lane]      + v1 * a[lane + 32];
    float s2 = v0 * a[64 + lane] + v1 * a[96 + lane];
#pragma unroll
    for (int o = 16; o; o >>= 1) {
        s1 += __shfl_xor_sync(0xffffffffu, s1, o);
        s2 += __shfl_xor_sync(0xffffffffu, s2, o);
    }
    if (lane == 0) { g_a1[warp] = s1; g_a2[warp] = s2; }
}

// ---------------------------------------------------------------------------
// K2bc: fused max(a2) + exp-factor precompute.
//   s>=0: exp(s-M)=e1p_i*e2p_j ;  s<0: exp(a*s-M)=e1n_i*e2n_j
// ---------------------------------------------------------------------------
__global__ __launch_bounds__(256) void k2bc_pre() {
    __shared__ float sm[256];
    float m = -1e30f;
    for (int i = threadIdx.x; i < NROWS; i += 256) m = fmaxf(m, g_a2[i]);
    sm[threadIdx.x] = m;
    __syncthreads();
    for (int s = 128; s; s >>= 1) {
        if (threadIdx.x < s) sm[threadIdx.x] = fmaxf(sm[threadIdx.x], sm[threadIdx.x + s]);
        __syncthreads();
    }
    const float a2m = sm[0];
    const int i = blockIdx.x * 256 + threadIdx.x;
    float a2i = g_a2[i];
    float sM = g_a1[i] + a2m;
    float M = fmaxf(sM, ALPHA * sM);
    g_e1p[i] = expf(sM - M);
    g_e1n[i] = expf(ALPHA * sM - M);
    float d = a2i - a2m;
    g_a2h[i]  = __float2half(a2i);
    g_e2ph[i] = __float2half(expf(d));
    g_e2nh[i] = __float2half(expf(ALPHA * d));
}

// ---------------------------------------------------------------------------
// K3: fused masked-softmax + att@h. fp16 mma + ldmatrix. Latency-stripped
// pipeline: s2 factors resident in SMEM for the whole JCHUNK (loaded once),
// H tile register-prefetched (PF1, STS from regs at tile top), adj register-
// prefetched at depth 2. One __syncthreads per tile; its STS drain now has
// no LDG feeding it.
// ---------------------------------------------------------------------------
__global__ __launch_bounds__(256) void k3_fused(const float* __restrict__ adj) {
    __shared__ __align__(16) __half Ps[2][64][72];  // 18432 B
    __shared__ __align__(16) __half Hs[2][64][72];  // 18432 B
    __shared__ __align__(16) __half S2[3][JCHUNK];  // 12288 B  (a2h/e2ph/e2nh)

    const int tid = threadIdx.x;
    const int row0 = blockIdx.x * 64;
    const int split = blockIdx.y;
    const int jbase = split * JCHUNK;

    // P-build mapping: thread -> (row pr, 16 j's from pj)
    const int pr = tid >> 2;
    const int pj = (tid & 3) << 4;
    const unsigned a1u  = h2u(__float2half2_rn(g_a1[row0 + pr]));
    const unsigned e1pu = h2u(__float2half2_rn(g_e1p[row0 + pr]));
    const unsigned e1nu = h2u(__float2half2_rn(g_e1n[row0 + pr]));
    const __half2 hzero = __float2half2_rn(0.f);

    // mma mapping
    const int lane = tid & 31, warp = tid >> 5;
    const int wy = warp >> 1, wx = warp & 1;
    const int g = lane >> 2, t4 = lane & 3;
    const unsigned ONEH2 = 0x3C003C00u;
    float acc[4][4];
#pragma unroll
    for (int nf = 0; nf < 4; nf++)
#pragma unroll
        for (int c = 0; c < 4; c++) acc[nf][c] = 0.f;
    float accD[4] = {0.f, 0.f, 0.f, 0.f};

    // ldmatrix addresses (pitch 144B, verified conflict-free)
    const uint32_t PITCH = 72 * 2;
    const uint32_t BUFSZ = 64 * PITCH;
    const uint32_t aRow = wy * 16 + (lane & 15);
    const uint32_t aK   = (lane >> 4) * 8;
    const uint32_t aBase = smem_u32(&Ps[0][0][0]) + aRow * PITCH + aK * 2;
    const uint32_t bRow = wx * 32 + ((lane >> 4) << 3) + (lane & 7);
    const uint32_t bK   = ((lane >> 3) & 1) * 8;
    const uint32_t bBase = smem_u32(&Hs[0][0][0]) + bRow * PITCH + bK * 2;

    // H-load mapping: 4 threads per col, 16 halves each
    const int hcol = tid >> 2, hpart = tid & 3;
    const __half* hsrc = g_hT + (size_t)hcol * NROWS + jbase + hpart * 16;

    const float* arow = adj + (size_t)(row0 + pr) * NROWS + jbase + pj;

    // ---- prologue ----
    // whole-JCHUNK s2 factors into SMEM (each thread: 3 x 16B)
    {
        const __half* srcs[3] = {g_a2h + jbase, g_e2ph + jbase, g_e2nh + jbase};
#pragma unroll
        for (int k = 0; k < 3; k++)
            *(uint4*)&S2[k][tid * 8] = *(const uint4*)(srcs[k] + tid * 8);
    }
    // adj tiles 0 and 1 into registers (PF depth 2)
    float4 aregs2[2][4];
#pragma unroll
    for (int q = 0; q < 4; q++) aregs2[0][q] = *(const float4*)(arow + q * 4);
#pragma unroll
    for (int q = 0; q < 4; q++) aregs2[1][q] = *(const float4*)(arow + 64 + q * 4);
    // H tile 0 into registers (PF depth 1)
    uint4 hr0 = ((const uint4*)hsrc)[0];
    uint4 hr1 = ((const uint4*)hsrc)[1];
    __syncthreads();

    for (int jt = 0; jt < JCHUNK; jt += 64) {
        const int buf = (jt >> 6) & 1;

        // --- stage A: H STS from regs (no memory latency), P-build ---
        *(uint4*)&Hs[buf][hcol][hpart * 16]     = hr0;
        *(uint4*)&Hs[buf][hcol][hpart * 16 + 8] = hr1;

        unsigned pph[8];
#pragma unroll
        for (int hh = 0; hh < 2; hh++) {
            uint4 A2 = *(const uint4*)&S2[0][jt + pj + hh * 8];
            uint4 EP = *(const uint4*)&S2[1][jt + pj + hh * 8];
            uint4 EN = *(const uint4*)&S2[2][jt + pj + hh * 8];
            unsigned a2w[4] = {A2.x, A2.y, A2.z, A2.w};
            unsigned epw[4] = {EP.x, EP.y, EP.z, EP.w};
            unsigned enw[4] = {EN.x, EN.y, EN.z, EN.w};
#pragma unroll
            for (int q2 = 0; q2 < 2; q2++) {
                float4 av = aregs2[buf][hh * 2 + q2];
#pragma unroll
                for (int sub = 0; sub < 2; sub++) {
                    const int k = q2 * 2 + sub;
                    unsigned adjw = h2u(sub == 0 ? __floats2half2_rn(av.x, av.y)
                                                 : __floats2half2_rn(av.z, av.w));
                    unsigned s = h2u(__hadd2(u2h(a1u), u2h(a2w[k])));
                    unsigned m = __hge2_mask(u2h(s), hzero);
                    unsigned f1 = (e1pu & m) | (e1nu & ~m);
                    unsigned f2 = (epw[k] & m) | (enw[k] & ~m);
                    pph[hh * 4 + k] =
                        h2u(__hmul2(__hmul2(u2h(f1), u2h(f2)), u2h(adjw)));
                }
            }
        }
        *(uint4*)&Ps[buf][pr][pj]     = make_uint4(pph[0], pph[1], pph[2], pph[3]);
        *(uint4*)&Ps[buf][pr][pj + 8] = make_uint4(pph[4], pph[5], pph[6], pph[7]);

        // --- prefetch: adj tile t+2 (into just-consumed slot), H tile t+1 ---
        if (jt + 128 < JCHUNK) {
            const float* an = arow + jt + 128;
#pragma unroll
            for (int q = 0; q < 4; q++) aregs2[buf][q] = *(const float4*)(an + q * 4);
        }
        if (jt + 64 < JCHUNK) {
            const uint4* hn = (const uint4*)(hsrc + jt + 64);
            hr0 = hn[0];
            hr1 = hn[1];
        }
        __syncthreads();

        // --- stage B: ldmatrix fragments + fp16 mma ---
        const uint32_t aB = aBase + buf * BUFSZ;
        const uint32_t bB = bBase + buf * BUFSZ;
#pragma unroll
        for (int kk = 0; kk < 4; kk++) {
            const uint32_t kby = kk * 32;
            unsigned a0, a1, a2, a3;
            ldsm_x4(a0, a1, a2, a3, aB + kby);
            unsigned b00, b01, b10, b11;
            ldsm_x4(b00, b01, b10, b11, bB + kby);
            unsigned b20, b21, b30, b31;
            ldsm_x4(b20, b21, b30, b31, bB + 16 * PITCH + kby);
            if (wx == 0) mma_f16(accD, a0, a1, a2, a3, ONEH2, ONEH2);
            mma_f16(acc[0], a0, a1, a2, a3, b00, b01);
            mma_f16(acc[1], a0, a1, a2, a3, b10, b11);
            mma_f16(acc[2], a0, a1, a2, a3, b20, b21);
            mma_f16(acc[3], a0, a1, a2, a3, b30, b31);
        }
    }

    // denominator: every column of accD equals the row sum
    if (wx == 0 && t4 == 0) {
        g_pden[split][row0 + wy * 16 + g]     = accD[0];
        g_pden[split][row0 + wy * 16 + g + 8] = accD[2];
    }

    // partial accumulator
    float* pa = g_pacc[split];
#pragma unroll
    for (int nf = 0; nf < 4; nf++) {
        const int col = wx * 32 + nf * 8 + t4 * 2;
        const int r = row0 + wy * 16 + g;
        *(float2*)&pa[(size_t)r * FOUT + col]       = make_float2(acc[nf][0], acc[nf][1]);
        *(float2*)&pa[(size_t)(r + 8) * FOUT + col] = make_float2(acc[nf][2], acc[nf][3]);
    }
}

// ---------------------------------------------------------------------------
// K4: epilogue — merge split-j partials, normalize, ELU, write out.
// ---------------------------------------------------------------------------
__global__ __launch_bounds__(256) void k4_epi(float* __restrict__ out) {
    const int idx = blockIdx.x * 256 + threadIdx.x;
    const int row = idx >> 4;
    const int cg = (idx & 15) << 2;
    float4 v = make_float4(0.f, 0.f, 0.f, 0.f);
    float den = 0.f;
#pragma unroll
    for (int s = 0; s < JSPLIT; s++) {
        float4 p = *(const float4*)&g_pacc[s][(size_t)row * FOUT + cg];
        v.x += p.x; v.y += p.y; v.z += p.z; v.w += p.w;
        den += g_pden[s][row];
    }
    float inv = 1.f / den;
    float4 r;
    float t0 = v.x * inv; r.x = t0 > 0.f ? t0 : expm1f(t0);
    float t1 = v.y * inv; r.y = t1 > 0.f ? t1 : expm1f(t1);
    float t2 = v.z * inv; r.z = t2 > 0.f ? t2 : expm1f(t2);
    float t3 = v.w * inv; r.w = t3 > 0.f ? t3 : expm1f(t3);
    *(float4*)&out[(size_t)row * FOUT + cg] = r;
}

// ---------------------------------------------------------------------------
extern "C" void kernel_launch(void* const* d_in, const int* in_sizes, int n_in,
                              void* d_out, int out_size) {
    const float *x = nullptr, *adj = nullptr, *W = nullptr, *a = nullptr;
    for (int i = 0; i < n_in; i++) {
        switch (in_sizes[i]) {
            case NROWS * FIN:   x   = (const float*)d_in[i]; break;
            case NROWS * NROWS: adj = (const float*)d_in[i]; break;
            case FIN * FOUT:    W   = (const float*)d_in[i]; break;
            case 2 * FOUT:      a   = (const float*)d_in[i]; break;
        }
    }
    float* out = (float*)d_out;

    k1_gemm<<<NROWS / 64, 256>>>(x, W);
    k1t_trans<<<NROWS / 64, 256>>>();
    k2_att<<<NROWS / 8, 256>>>(a);
    k2bc_pre<<<NROWS / 256, 256>>>();
    dim3 g3(NROWS / 64, JSPLIT);
    k3_fused<<<g3, 256>>>(adj);
    k4_epi<<<NROWS * FOUT / 4 / 256, 256>>>(out);
}

// round 12
// speedup vs baseline: 1.2065x; 1.2065x over previous
#include <cuda_runtime.h>
#include <cuda_fp16.h>
#include <math.h>
#include <stdint.h>

#define NROWS 8192
#define FIN   512
#define FOUT  64
#define ALPHA 0.2f
#define JSPLIT 8
#define JCHUNK (NROWS / JSPLIT)

// Scratch (no cudaMalloc allowed)
__device__ __align__(16) float  g_h[NROWS * FOUT];    // h = x @ W (fp32)
__device__ __align__(16) __half g_hT[FOUT * NROWS];   // h transposed, fp16: [col][row]
__device__ float  g_a1[NROWS];
__device__ float  g_a2[NROWS];
__device__ float  g_e1p[NROWS], g_e1n[NROWS];           // per-row factors (fp32)
__device__ __align__(16) __half g_a2h[NROWS];           // fp16 copies for k3
__device__ __align__(16) __half g_e2ph[NROWS];
__device__ __align__(16) __half g_e2nh[NROWS];
__device__ __align__(16) float g_pacc[JSPLIT][NROWS * FOUT];
__device__ float  g_pden[JSPLIT][NROWS];

__device__ __forceinline__ unsigned h2u(__half2 h) { return *(unsigned*)&h; }
__device__ __forceinline__ __half2 u2h(unsigned u) { return *(__half2*)&u; }

__device__ __forceinline__ uint32_t smem_u32(const void* p) {
    uint32_t a;
    asm("{ .reg .u64 t; cvta.to.shared.u64 t, %1; cvt.u32.u64 %0, t; }" : "=r"(a) : "l"(p));
    return a;
}

__device__ __forceinline__ void mma_f16(float c[4],
                                        unsigned a0, unsigned a1, unsigned a2, unsigned a3,
                                        unsigned b0, unsigned b1) {
    asm volatile(
        "mma.sync.aligned.m16n8k16.row.col.f32.f16.f16.f32 "
        "{%0,%1,%2,%3}, {%4,%5,%6,%7}, {%8,%9}, {%0,%1,%2,%3};"
        : "+f"(c[0]), "+f"(c[1]), "+f"(c[2]), "+f"(c[3])
        : "r"(a0), "r"(a1), "r"(a2), "r"(a3), "r"(b0), "r"(b1));
}

__device__ __forceinline__ void ldsm_x4(unsigned& r0, unsigned& r1,
                                        unsigned& r2, unsigned& r3, uint32_t addr) {
    asm volatile("ldmatrix.sync.aligned.m8n8.x4.shared.b16 {%0,%1,%2,%3}, [%4];"
                 : "=r"(r0), "=r"(r1), "=r"(r2), "=r"(r3) : "r"(addr));
}

// ---------------------------------------------------------------------------
// K1: h = x @ W  +  fused write of g_hT (fp16 transposed copy).
// FP32, 64x64 CTA tile, 4x4 per thread.
// ---------------------------------------------------------------------------
__global__ __launch_bounds__(256) void k1_gemm(const float* __restrict__ x,
                                               const float* __restrict__ W) {
    __shared__ __align__(16) float xT[32][68];
    __shared__ __align__(16) float Ws[32][68];
    const int tid = threadIdx.x;
    const int ty = tid >> 4, tx = tid & 15;
    const int row0 = blockIdx.x * 64;

    float acc[4][4];
#pragma unroll
    for (int i = 0; i < 4; i++)
#pragma unroll
        for (int j = 0; j < 4; j++) acc[i][j] = 0.f;

    for (int k0 = 0; k0 < FIN; k0 += 32) {
#pragma unroll
        for (int l = 0; l < 2; l++) {
            int idx = tid * 2 + l;
            int r = idx >> 3;
            int kq = (idx & 7) << 2;
            float4 v = *(const float4*)(x + (size_t)(row0 + r) * FIN + k0 + kq);
            xT[kq + 0][r] = v.x; xT[kq + 1][r] = v.y;
            xT[kq + 2][r] = v.z; xT[kq + 3][r] = v.w;
        }
#pragma unroll
        for (int l = 0; l < 2; l++) {
            int idx = tid * 2 + l;
            int kk = idx >> 4;
            int cq = (idx & 15) << 2;
            *(float4*)&Ws[kk][cq] = *(const float4*)(W + (size_t)(k0 + kk) * FOUT + cq);
        }
        __syncthreads();
#pragma unroll
        for (int kk = 0; kk < 32; kk++) {
            float4 xa = *(const float4*)&xT[kk][ty * 4];
            float4 wb = *(const float4*)&Ws[kk][tx * 4];
            float av[4] = {xa.x, xa.y, xa.z, xa.w};
            float bv[4] = {wb.x, wb.y, wb.z, wb.w};
#pragma unroll
            for (int i = 0; i < 4; i++)
#pragma unroll
                for (int j = 0; j < 4; j++)
                    acc[i][j] = fmaf(av[i], bv[j], acc[i][j]);
        }
        __syncthreads();
    }
#pragma unroll
    for (int i = 0; i < 4; i++) {
        float4 v = make_float4(acc[i][0], acc[i][1], acc[i][2], acc[i][3]);
        *(float4*)(g_h + (size_t)(row0 + ty * 4 + i) * FOUT + tx * 4) = v;
    }
    // fused hT: col = tx*4+j, rows row0+ty*4 .. +3 (two half2 stores per col)
#pragma unroll
    for (int j = 0; j < 4; j++) {
        const int col = tx * 4 + j;
        __half* dst = g_hT + (size_t)col * NROWS + row0 + ty * 4;
        __half2 lo = __floats2half2_rn(acc[0][j], acc[1][j]);
        __half2 hi = __floats2half2_rn(acc[2][j], acc[3][j]);
        *(__half2*)dst       = lo;
        *(__half2*)(dst + 2) = hi;
    }
}

// ---------------------------------------------------------------------------
// K2: a1/a2 row projections. One warp per row.
// ---------------------------------------------------------------------------
__global__ __launch_bounds__(256) void k2_att(const float* __restrict__ a) {
    const int warp = (blockIdx.x * blockDim.x + threadIdx.x) >> 5;
    const int lane = threadIdx.x & 31;
    if (warp >= NROWS) return;
    const float* hrow = g_h + (size_t)warp * FOUT;
    float v0 = hrow[lane], v1 = hrow[lane + 32];
    float s1 = v0 * a[lane]      + v1 * a[lane + 32];
    float s2 = v0 * a[64 + lane] + v1 * a[96 + lane];
#pragma unroll
    for (int o = 16; o; o >>= 1) {
        s1 += __shfl_xor_sync(0xffffffffu, s1, o);
        s2 += __shfl_xor_sync(0xffffffffu, s2, o);
    }
    if (lane == 0) { g_a1[warp] = s1; g_a2[warp] = s2; }
}

// ---------------------------------------------------------------------------
// K2bc: fused max(a2) + exp-factor precompute.
//   s>=0: exp(s-M)=e1p_i*e2p_j ;  s<0: exp(a*s-M)=e1n_i*e2n_j
// ---------------------------------------------------------------------------
__global__ __launch_bounds__(256) void k2bc_pre() {
    __shared__ float sm[256];
    float m = -1e30f;
    for (int i = threadIdx.x; i < NROWS; i += 256) m = fmaxf(m, g_a2[i]);
    sm[threadIdx.x] = m;
    __syncthreads();
    for (int s = 128; s; s >>= 1) {
        if (threadIdx.x < s) sm[threadIdx.x] = fmaxf(sm[threadIdx.x], sm[threadIdx.x + s]);
        __syncthreads();
    }
    const float a2m = sm[0];
    const int i = blockIdx.x * 256 + threadIdx.x;
    float a2i = g_a2[i];
    float sM = g_a1[i] + a2m;
    float M = fmaxf(sM, ALPHA * sM);
    g_e1p[i] = expf(sM - M);
    g_e1n[i] = expf(ALPHA * sM - M);
    float d = a2i - a2m;
    g_a2h[i]  = __float2half(a2i);
    g_e2ph[i] = __float2half(expf(d));
    g_e2nh[i] = __float2half(expf(ALPHA * d));
}

// ---------------------------------------------------------------------------
// K3: fused masked-softmax + att@h. fp16 mma m16n8k16 + ldmatrix.x4.
// Half2 P-build, denominator via mma with B=ones, single-sync ping-pong.
// CTA: 64 rows x JCHUNK j (JSPLIT=8 -> 1024 CTAs). 8 warps: wy x wx.
// ---------------------------------------------------------------------------
__global__ __launch_bounds__(256) void k3_fused(const float* __restrict__ adj) {
    __shared__ __align__(16) __half Ps[2][64][72];  // [buf][row][j], pitch 144B
    __shared__ __align__(16) __half Hs[2][64][72];  // [buf][col][j]
    __shared__ __align__(16) __half s2h[2][3][64];  // [buf][a2h/e2ph/e2nh][j]

    const int tid = threadIdx.x;
    const int row0 = blockIdx.x * 64;
    const int split = blockIdx.y;
    const int jbase = split * JCHUNK;

    // P-build mapping: thread -> (row pr, 16 j's from pj)
    const int pr = tid >> 2;
    const int pj = (tid & 3) << 4;
    const unsigned a1u  = h2u(__float2half2_rn(g_a1[row0 + pr]));
    const unsigned e1pu = h2u(__float2half2_rn(g_e1p[row0 + pr]));
    const unsigned e1nu = h2u(__float2half2_rn(g_e1n[row0 + pr]));
    const __half2 hzero = __float2half2_rn(0.f);

    // mma mapping
    const int lane = tid & 31, warp = tid >> 5;
    const int wy = warp >> 1, wx = warp & 1;
    const int g = lane >> 2, t4 = lane & 3;
    const unsigned ONEH2 = 0x3C003C00u;
    float acc[4][4];
#pragma unroll
    for (int nf = 0; nf < 4; nf++)
#pragma unroll
        for (int c = 0; c < 4; c++) acc[nf][c] = 0.f;
    float accD[4] = {0.f, 0.f, 0.f, 0.f};

    // ldmatrix addresses (pitch 144B, conflict-free)
    const uint32_t PITCH = 72 * 2;
    const uint32_t BUFSZ = 64 * PITCH;
    const uint32_t aRow = wy * 16 + (lane & 15);
    const uint32_t aK   = (lane >> 4) * 8;
    const uint32_t aBase = smem_u32(&Ps[0][0][0]) + aRow * PITCH + aK * 2;
    const uint32_t bRow = wx * 32 + ((lane >> 4) << 3) + (lane & 7);
    const uint32_t bK   = ((lane >> 3) & 1) * 8;
    const uint32_t bBase = smem_u32(&Hs[0][0][0]) + bRow * PITCH + bK * 2;

    // H-load mapping: 4 threads per col, 16 halves each
    const int hcol = tid >> 2, hpart = tid & 3;
    const __half* hsrc = g_hT + (size_t)hcol * NROWS + jbase + hpart * 16;

    // s2 staging (threads 0..23)
    const int s2w = tid >> 3, s2part = tid & 7;
    const __half* s2src =
        (s2w == 0 ? g_a2h : (s2w == 1 ? g_e2ph : g_e2nh)) + jbase + s2part * 8;

    const float* arow = adj + (size_t)(row0 + pr) * NROWS + jbase + pj;

    // prologue: adj tile 0 regs + s2 tile 0 into buf 0
    float4 aregs[4];
#pragma unroll
    for (int q = 0; q < 4; q++) aregs[q] = *(const float4*)(arow + q * 4);
    if (tid < 24) *(uint4*)&s2h[0][s2w][s2part * 8] = *(const uint4*)s2src;
    __syncthreads();

    for (int jt = 0; jt < JCHUNK; jt += 64) {
        const int buf = (jt >> 6) & 1;

        // --- stage A: H tile load + half2 P-build ---
        {
            const uint4* src = (const uint4*)(hsrc + jt);
            *(uint4*)&Hs[buf][hcol][hpart * 16]     = src[0];
            *(uint4*)&Hs[buf][hcol][hpart * 16 + 8] = src[1];
        }
        unsigned pph[8];
#pragma unroll
        for (int hh = 0; hh < 2; hh++) {
            uint4 A2 = *(const uint4*)&s2h[buf][0][pj + hh * 8];
            uint4 EP = *(const uint4*)&s2h[buf][1][pj + hh * 8];
            uint4 EN = *(const uint4*)&s2h[buf][2][pj + hh * 8];
            unsigned a2w[4] = {A2.x, A2.y, A2.z, A2.w};
            unsigned epw[4] = {EP.x, EP.y, EP.z, EP.w};
            unsigned enw[4] = {EN.x, EN.y, EN.z, EN.w};
#pragma unroll
            for (int q2 = 0; q2 < 2; q2++) {
                float4 av = aregs[hh * 2 + q2];
#pragma unroll
                for (int sub = 0; sub < 2; sub++) {
                    const int k = q2 * 2 + sub;
                    unsigned adjw = h2u(sub == 0 ? __floats2half2_rn(av.x, av.y)
                                                 : __floats2half2_rn(av.z, av.w));
                    unsigned s = h2u(__hadd2(u2h(a1u), u2h(a2w[k])));
                    unsigned m = __hge2_mask(u2h(s), hzero);
                    unsigned f1 = (e1pu & m) | (e1nu & ~m);
                    unsigned f2 = (epw[k] & m) | (enw[k] & ~m);
                    pph[hh * 4 + k] =
                        h2u(__hmul2(__hmul2(u2h(f1), u2h(f2)), u2h(adjw)));
                }
            }
        }
        *(uint4*)&Ps[buf][pr][pj]     = make_uint4(pph[0], pph[1], pph[2], pph[3]);
        *(uint4*)&Ps[buf][pr][pj + 8] = make_uint4(pph[4], pph[5], pph[6], pph[7]);

        // --- prefetch tile t+1 ---
        if (jt + 64 < JCHUNK) {
            const float* an = arow + jt + 64;
#pragma unroll
            for (int q = 0; q < 4; q++) aregs[q] = *(const float4*)(an + q * 4);
            if (tid < 24)
                *(uint4*)&s2h[buf ^ 1][s2w][s2part * 8] =
                    *(const uint4*)(s2src + jt + 64);
        }
        __syncthreads();

        // --- stage B: ldmatrix fragments + fp16 mma ---
        const uint32_t aB = aBase + buf * BUFSZ;
        const uint32_t bB = bBase + buf * BUFSZ;
#pragma unroll
        for (int kk = 0; kk < 4; kk++) {
            const uint32_t kby = kk * 32;
            unsigned a0, a1, a2, a3;
            ldsm_x4(a0, a1, a2, a3, aB + kby);
            unsigned b00, b01, b10, b11;
            ldsm_x4(b00, b01, b10, b11, bB + kby);
            unsigned b20, b21, b30, b31;
            ldsm_x4(b20, b21, b30, b31, bB + 16 * PITCH + kby);
            if (wx == 0) mma_f16(accD, a0, a1, a2, a3, ONEH2, ONEH2);
            mma_f16(acc[0], a0, a1, a2, a3, b00, b01);
            mma_f16(acc[1], a0, a1, a2, a3, b10, b11);
            mma_f16(acc[2], a0, a1, a2, a3, b20, b21);
            mma_f16(acc[3], a0, a1, a2, a3, b30, b31);
        }
    }

    // denominator: every column of accD equals the row sum
    if (wx == 0 && t4 == 0) {
        g_pden[split][row0 + wy * 16 + g]     = accD[0];
        g_pden[split][row0 + wy * 16 + g + 8] = accD[2];
    }

    // partial accumulator
    float* pa = g_pacc[split];
#pragma unroll
    for (int nf = 0; nf < 4; nf++) {
        const int col = wx * 32 + nf * 8 + t4 * 2;
        const int r = row0 + wy * 16 + g;
        *(float2*)&pa[(size_t)r * FOUT + col]       = make_float2(acc[nf][0], acc[nf][1]);
        *(float2*)&pa[(size_t)(r + 8) * FOUT + col] = make_float2(acc[nf][2], acc[nf][3]);
    }
}

// ---------------------------------------------------------------------------
// K4: epilogue — merge split-j partials, normalize, ELU, write out.
// ---------------------------------------------------------------------------
__global__ __launch_bounds__(256) void k4_epi(float* __restrict__ out) {
    const int idx = blockIdx.x * 256 + threadIdx.x;
    const int row = idx >> 4;
    const int cg = (idx & 15) << 2;
    float4 v = make_float4(0.f, 0.f, 0.f, 0.f);
    float den = 0.f;
#pragma unroll
    for (int s = 0; s < JSPLIT; s++) {
        float4 p = *(const float4*)&g_pacc[s][(size_t)row * FOUT + cg];
        v.x += p.x; v.y += p.y; v.z += p.z; v.w += p.w;
        den += g_pden[s][row];
    }
    float inv = 1.f / den;
    float4 r;
    float t0 = v.x * inv; r.x = t0 > 0.f ? t0 : expm1f(t0);
    float t1 = v.y * inv; r.y = t1 > 0.f ? t1 : expm1f(t1);
    float t2 = v.z * inv; r.z = t2 > 0.f ? t2 : expm1f(t2);
    float t3 = v.w * inv; r.w = t3 > 0.f ? t3 : expm1f(t3);
    *(float4*)&out[(size_t)row * FOUT + cg] = r;
}

// ---------------------------------------------------------------------------
extern "C" void kernel_launch(void* const* d_in, const int* in_sizes, int n_in,
                              void* d_out, int out_size) {
    const float *x = nullptr, *adj = nullptr, *W = nullptr, *a = nullptr;
    for (int i = 0; i < n_in; i++) {
        switch (in_sizes[i]) {
            case NROWS * FIN:   x   = (const float*)d_in[i]; break;
            case NROWS * NROWS: adj = (const float*)d_in[i]; break;
            case FIN * FOUT:    W   = (const float*)d_in[i]; break;
            case 2 * FOUT:      a   = (const float*)d_in[i]; break;
        }
    }
    float* out = (float*)d_out;

    k1_gemm<<<NROWS / 64, 256>>>(x, W);      // launch 1 (writes g_h + g_hT)
    k2_att<<<NROWS / 8, 256>>>(a);           // launch 2
    k2bc_pre<<<NROWS / 256, 256>>>();        // launch 3
    dim3 g3(NROWS / 64, JSPLIT);
    k3_fused<<<g3, 256>>>(adj);              // launch 4  (ncu captures here)
    k4_epi<<<NROWS * FOUT / 4 / 256, 256>>>(out);  // launch 5
}